// round 7
// baseline (speedup 1.0000x reference)
#include <cuda_runtime.h>

// Problem constants (match reference)
#define N_FEAT_COLS 9
#define CARD 50000
#define EMB 128
#define EDGE_DIM 27

#define BLOCK 256
#define WPB (BLOCK / 32)

__device__ float g_v[EDGE_DIM];
__device__ float g_c;

__global__ void precompute_v_kernel(const float* __restrict__ edge_w,
                                    const float* __restrict__ edge_b,
                                    const float* __restrict__ out_w,
                                    const float* __restrict__ out_b) {
    int j = threadIdx.x;
    if (j < EDGE_DIM) {
        float s = 0.f;
        #pragma unroll 8
        for (int k = 0; k < EMB; k++) s += out_w[k] * edge_w[k * EDGE_DIM + j];
        g_v[j] = s;
    }
    if (j == EDGE_DIM) {
        float s = out_b[0];
        #pragma unroll 8
        for (int k = 0; k < EMB; k++) s += out_w[k] * edge_b[k];
        g_c = s;
    }
}

__device__ __forceinline__ float4 ld4(const float* __restrict__ p) {
    return *reinterpret_cast<const float4*>(p);
}

// Table gather: L2-only (no L1 allocation — table has ~zero L1 reuse and
// would evict the x rows / emb_type that do reuse L1).
__device__ __forceinline__ float4 ld4cg(const float* __restrict__ p) {
    return __ldcg(reinterpret_cast<const float4*>(p));
}

// Encode one node's 128-dim embedding; each lane holds 4 contiguous floats.
__device__ __forceinline__ float4 encode_node(int rv, int base, int lane4,
                                              const float* __restrict__ emb_type,
                                              const float* __restrict__ emb_feats) {
    const unsigned FULL = 0xffffffffu;
    int t = __shfl_sync(FULL, rv, base);  // type (uniform across warp)
    float4 acc = ld4(emb_type + t * EMB + lane4);   // tiny, L1-resident
    // TYPE_PER_COL = (0,0,0,0,1,2,2,2,2)
    int h0 = (t == 0) ? 0 : (t == 1) ? 4 : 5;
    int nh = (t == 1) ? 1 : 4;
    #pragma unroll 4
    for (int i = 0; i < 4; i++) {
        if (i < nh) {
            int h = h0 + i;
            int f = __shfl_sync(FULL, rv, base + h + 1);
            float4 e = ld4cg(emb_feats + ((long long)h * CARD + f) * EMB + lane4);
            acc.x += e.x; acc.y += e.y; acc.z += e.z; acc.w += e.w;
        }
    }
    return acc;
}

// Load one edge's indices, x rows (cooperative) and msg partial.
__device__ __forceinline__ void load_edge(int e, int lane,
                                          const int* __restrict__ x,
                                          const int* __restrict__ src,
                                          const int* __restrict__ dst,
                                          const int* __restrict__ neg_dst,
                                          const float* __restrict__ msg,
                                          int& rv, float& m) {
    int s  = __ldcs(src + e);
    int d  = __ldcs(dst + e);
    int nd = __ldcs(neg_dst + e);
    int which = lane / 10;          // 0:src 1:dst 2:neg
    int off   = lane - which * 10;
    int nid   = (which == 0) ? s : (which == 1) ? d : nd;
    rv = 0;
    if (lane < 30) rv = __ldg(x + (long long)nid * 10 + off);
    m = 0.f;
    if (lane < EDGE_DIM)
        m = __ldcs(msg + (long long)e * EDGE_DIM + lane) * g_v[lane];
}

__global__ __launch_bounds__(BLOCK)
void edge_pred_kernel(const int* __restrict__ x,
                      const int* __restrict__ src,
                      const int* __restrict__ dst,
                      const int* __restrict__ neg_dst,
                      const float* __restrict__ msg,
                      const float* __restrict__ emb_type,
                      const float* __restrict__ emb_feats,
                      const float* __restrict__ out_w,
                      float* __restrict__ out,
                      int E) {
    const unsigned FULL = 0xffffffffu;
    int lane = threadIdx.x & 31;
    int gw   = blockIdx.x * WPB + (threadIdx.x >> 5);
    int TW   = gridDim.x * WPB;
    int lane4 = lane * 4;

    float4 ow = ld4(out_w + lane4);
    float  c0 = g_c;

    int e = gw;
    int rv; float m;
    if (e < E) load_edge(e, lane, x, src, dst, neg_dst, msg, rv, m);

    while (e < E) {
        int e_next = e + TW;

        // Gathers for the current edge issue right away (rv is ready).
        float4 hs = encode_node(rv, 0,  lane4, emb_type, emb_feats);
        float4 hd = encode_node(rv, 10, lane4, emb_type, emb_feats);
        float4 hn = encode_node(rv, 20, lane4, emb_type, emb_feats);

        // Prefetch next edge's index chain while gathers are in flight.
        int rv2 = 0; float m2 = 0.f;
        if (e_next < E)
            load_edge(e_next, lane, x, src, dst, neg_dst, msg, rv2, m2);

        float pp = fmaxf(hs.x + hd.x, 0.f) * ow.x
                 + fmaxf(hs.y + hd.y, 0.f) * ow.y
                 + fmaxf(hs.z + hd.z, 0.f) * ow.z
                 + fmaxf(hs.w + hd.w, 0.f) * ow.w;
        float np = fmaxf(hs.x + hn.x, 0.f) * ow.x
                 + fmaxf(hs.y + hn.y, 0.f) * ow.y
                 + fmaxf(hs.z + hn.z, 0.f) * ow.z
                 + fmaxf(hs.w + hn.w, 0.f) * ow.w;
        pp += m;
        np += m;

        #pragma unroll
        for (int o = 16; o > 0; o >>= 1) {
            pp += __shfl_xor_sync(FULL, pp, o);
            np += __shfl_xor_sync(FULL, np, o);
        }

        if (lane == 0) {
            __stcs(out + e,     pp + c0);   // pos
            __stcs(out + E + e, np + c0);   // neg
        }

        e = e_next;
        rv = rv2;
        m  = m2;
    }
}

extern "C" void kernel_launch(void* const* d_in, const int* in_sizes, int n_in,
                              void* d_out, int out_size) {
    const int*   x        = (const int*)  d_in[0];
    const int*   src      = (const int*)  d_in[1];
    const int*   dst      = (const int*)  d_in[2];
    const int*   neg_dst  = (const int*)  d_in[3];
    const float* msg      = (const float*)d_in[4];
    const float* emb_type = (const float*)d_in[5];
    const float* emb_feats= (const float*)d_in[6];
    const float* edge_w   = (const float*)d_in[7];
    const float* edge_b   = (const float*)d_in[8];
    const float* out_w    = (const float*)d_in[9];
    const float* out_b    = (const float*)d_in[10];
    float* out = (float*)d_out;

    int E = in_sizes[1];

    precompute_v_kernel<<<1, 32>>>(edge_w, edge_b, out_w, out_b);

    // Persistent-style launch: ~8 blocks per SM, warps loop over edges.
    int blocks = 148 * 8;
    edge_pred_kernel<<<blocks, BLOCK>>>(x, src, dst, neg_dst, msg,
                                        emb_type, emb_feats, out_w, out, E);
}

// round 8
// speedup vs baseline: 1.4614x; 1.4614x over previous
#include <cuda_runtime.h>
#include <cuda_fp16.h>

// Problem constants (match reference)
#define N_FEAT_COLS 9
#define CARD 50000
#define EMB 128
#define EDGE_DIM 27
#define TBL_ELEMS (N_FEAT_COLS * CARD * EMB)   // 57,600,000

// fp16 shadow of emb_feats (115.2 MB device scratch — static, not allocated)
__device__ __half g_tbl[TBL_ELEMS];

__device__ float g_v[EDGE_DIM];
__device__ float g_c;

__global__ void precompute_v_kernel(const float* __restrict__ edge_w,
                                    const float* __restrict__ edge_b,
                                    const float* __restrict__ out_w,
                                    const float* __restrict__ out_b) {
    int j = threadIdx.x;
    if (j < EDGE_DIM) {
        float s = 0.f;
        #pragma unroll 8
        for (int k = 0; k < EMB; k++) s += out_w[k] * edge_w[k * EDGE_DIM + j];
        g_v[j] = s;
    }
    if (j == EDGE_DIM) {
        float s = out_b[0];
        #pragma unroll 8
        for (int k = 0; k < EMB; k++) s += out_w[k] * edge_b[k];
        g_c = s;
    }
}

// Convert emb_feats (fp32) -> g_tbl (fp16). Pure streaming.
__global__ __launch_bounds__(256)
void convert_kernel(const float* __restrict__ src) {
    long long i = ((long long)blockIdx.x * blockDim.x + threadIdx.x) * 4;
    if (i >= TBL_ELEMS) return;
    float4 v = __ldcs(reinterpret_cast<const float4*>(src + i));
    __half2 lo = __floats2half2_rn(v.x, v.y);
    __half2 hi = __floats2half2_rn(v.z, v.w);
    uint2 u;
    u.x = *reinterpret_cast<unsigned*>(&lo);
    u.y = *reinterpret_cast<unsigned*>(&hi);
    *reinterpret_cast<uint2*>(g_tbl + i) = u;
}

__device__ __forceinline__ float4 ld4(const float* __restrict__ p) {
    return *reinterpret_cast<const float4*>(p);
}

// Gather 4 halves (8B per lane => one 256B warp load per row) and accumulate.
__device__ __forceinline__ void acc_h(float4& a, const __half* __restrict__ p) {
    uint2 u = __ldg(reinterpret_cast<const uint2*>(p));
    __half2 h0 = *reinterpret_cast<__half2*>(&u.x);
    __half2 h1 = *reinterpret_cast<__half2*>(&u.y);
    float2 f0 = __half22float2(h0);
    float2 f1 = __half22float2(h1);
    a.x += f0.x; a.y += f0.y; a.z += f1.x; a.w += f1.y;
}

// Encode one node's 128-dim embedding; each lane holds 4 contiguous dims.
__device__ __forceinline__ float4 encode_node(int rv, int base, int lane4,
                                              const float* __restrict__ emb_type) {
    const unsigned FULL = 0xffffffffu;
    int t = __shfl_sync(FULL, rv, base);  // type (uniform across warp)
    float4 acc = ld4(emb_type + t * EMB + lane4);
    // TYPE_PER_COL = (0,0,0,0,1,2,2,2,2)
    int h0 = (t == 0) ? 0 : (t == 1) ? 4 : 5;
    int nh = (t == 1) ? 1 : 4;
    #pragma unroll 4
    for (int i = 0; i < 4; i++) {
        if (i < nh) {
            int h = h0 + i;
            int f = __shfl_sync(FULL, rv, base + h + 1);
            acc_h(acc, g_tbl + ((long long)h * CARD + f) * EMB + lane4);
        }
    }
    return acc;
}

__global__ __launch_bounds__(256)
void edge_pred_kernel(const int* __restrict__ x,
                      const int* __restrict__ src,
                      const int* __restrict__ dst,
                      const int* __restrict__ neg_dst,
                      const float* __restrict__ msg,
                      const float* __restrict__ emb_type,
                      const float* __restrict__ out_w,
                      float* __restrict__ out,
                      int E) {
    const unsigned FULL = 0xffffffffu;
    int warp = (blockIdx.x * blockDim.x + threadIdx.x) >> 5;
    int lane = threadIdx.x & 31;
    if (warp >= E) return;
    int e = warp;

    int s  = __ldcs(src + e);
    int d  = __ldcs(dst + e);
    int nd = __ldcs(neg_dst + e);

    // Lanes 0..29 cooperatively load the three 10-int x rows in one LDG.
    int which = lane / 10;          // 0:src 1:dst 2:neg
    int off   = lane - which * 10;
    int nid   = (which == 0) ? s : (which == 1) ? d : nd;
    int rv = 0;
    if (lane < 30) rv = __ldcs(x + (long long)nid * 10 + off);

    // msg dot with precomputed v (streaming; issue early)
    float m = 0.f;
    if (lane < EDGE_DIM)
        m = __ldcs(msg + (long long)e * EDGE_DIM + lane) * g_v[lane];

    int lane4 = lane * 4;
    float4 hs = encode_node(rv, 0,  lane4, emb_type);
    float4 hd = encode_node(rv, 10, lane4, emb_type);
    float4 hn = encode_node(rv, 20, lane4, emb_type);

    float4 ow = ld4(out_w + lane4);

    float pp = fmaxf(hs.x + hd.x, 0.f) * ow.x
             + fmaxf(hs.y + hd.y, 0.f) * ow.y
             + fmaxf(hs.z + hd.z, 0.f) * ow.z
             + fmaxf(hs.w + hd.w, 0.f) * ow.w;
    float np = fmaxf(hs.x + hn.x, 0.f) * ow.x
             + fmaxf(hs.y + hn.y, 0.f) * ow.y
             + fmaxf(hs.z + hn.z, 0.f) * ow.z
             + fmaxf(hs.w + hn.w, 0.f) * ow.w;

    pp += m;
    np += m;

    #pragma unroll
    for (int o = 16; o > 0; o >>= 1) {
        pp += __shfl_xor_sync(FULL, pp, o);
        np += __shfl_xor_sync(FULL, np, o);
    }

    if (lane == 0) {
        float c = g_c;
        out[e]     = pp + c;   // pos
        out[E + e] = np + c;   // neg
    }
}

extern "C" void kernel_launch(void* const* d_in, const int* in_sizes, int n_in,
                              void* d_out, int out_size) {
    const int*   x        = (const int*)  d_in[0];
    const int*   src      = (const int*)  d_in[1];
    const int*   dst      = (const int*)  d_in[2];
    const int*   neg_dst  = (const int*)  d_in[3];
    const float* msg      = (const float*)d_in[4];
    const float* emb_type = (const float*)d_in[5];
    const float* emb_feats= (const float*)d_in[6];
    const float* edge_w   = (const float*)d_in[7];
    const float* edge_b   = (const float*)d_in[8];
    const float* out_w    = (const float*)d_in[9];
    const float* out_b    = (const float*)d_in[10];
    float* out = (float*)d_out;

    int E = in_sizes[1];

    precompute_v_kernel<<<1, 32>>>(edge_w, edge_b, out_w, out_b);

    // fp32 -> fp16 table conversion (streaming, ~345MB of traffic)
    int conv_threads = 256;
    int conv_blocks = (TBL_ELEMS / 4 + conv_threads - 1) / conv_threads;
    convert_kernel<<<conv_blocks, conv_threads>>>(emb_feats);

    int threads = 256;
    int warps_per_block = threads / 32;
    int blocks = (E + warps_per_block - 1) / warps_per_block;
    edge_pred_kernel<<<blocks, threads>>>(x, src, dst, neg_dst, msg,
                                          emb_type, out_w, out, E);
}

// round 10
// speedup vs baseline: 1.6686x; 1.1418x over previous
#include <cuda_runtime.h>
#include <cuda_fp16.h>

#define N_FEAT_COLS 9
#define CARD 50000
#define EMB 128
#define EDGE_DIM 27
#define TBL_ELEMS (N_FEAT_COLS * CARD * EMB)   // 57,600,000

// fp16 shadow of emb_feats (115.2 MB static device scratch)
__device__ __half g_tbl[TBL_ELEMS];

__device__ float g_v[EDGE_DIM];
__device__ float g_c;

// Parallel precompute: warp j computes g_v[j] (j<27) or g_c (j==27).
__global__ __launch_bounds__(1024)
void precompute_v_kernel(const float* __restrict__ edge_w,
                         const float* __restrict__ edge_b,
                         const float* __restrict__ out_w,
                         const float* __restrict__ out_b) {
    const unsigned FULL = 0xffffffffu;
    int w = threadIdx.x >> 5;
    int lane = threadIdx.x & 31;
    if (w > EDGE_DIM) return;
    float s = 0.f;
    if (w < EDGE_DIM) {
        for (int k = lane; k < EMB; k += 32)
            s += out_w[k] * edge_w[k * EDGE_DIM + w];
    } else {
        for (int k = lane; k < EMB; k += 32)
            s += out_w[k] * edge_b[k];
    }
    #pragma unroll
    for (int o = 16; o > 0; o >>= 1) s += __shfl_xor_sync(FULL, s, o);
    if (lane == 0) {
        if (w < EDGE_DIM) g_v[w] = s;
        else              g_c = s + out_b[0];
    }
}

// fp32 -> fp16 table conversion. Pure streaming.
__global__ __launch_bounds__(256)
void convert_kernel(const float* __restrict__ src) {
    long long i = ((long long)blockIdx.x * blockDim.x + threadIdx.x) * 4;
    if (i >= TBL_ELEMS) return;
    float4 v = __ldcs(reinterpret_cast<const float4*>(src + i));
    __half2 lo = __floats2half2_rn(v.x, v.y);
    __half2 hi = __floats2half2_rn(v.z, v.w);
    uint2 u;
    u.x = *reinterpret_cast<unsigned*>(&lo);
    u.y = *reinterpret_cast<unsigned*>(&hi);
    *reinterpret_cast<uint2*>(g_tbl + i) = u;
}

__device__ __forceinline__ float4 ld4(const float* __restrict__ p) {
    return *reinterpret_cast<const float4*>(p);
}

__device__ __forceinline__ void acc_u2(float4& a, uint2 u) {
    __half2 h0 = *reinterpret_cast<__half2*>(&u.x);
    __half2 h1 = *reinterpret_cast<__half2*>(&u.y);
    float2 f0 = __half22float2(h0);
    float2 f1 = __half22float2(h1);
    a.x += f0.x; a.y += f0.y; a.z += f1.x; a.w += f1.y;
}

// Issue the (up to) 4 table gathers for one node; results land in g[4].
__device__ __forceinline__ void issue_node(uint2* g, int h0, int nh,
                                           const int* f, int lane4) {
    const uint2 z = make_uint2(0u, 0u);
    #pragma unroll
    for (int i = 0; i < 4; i++) {
        const __half* p = g_tbl + ((long long)(h0 + i) * CARD + f[i]) * EMB + lane4;
        g[i] = (i < nh) ? __ldg(reinterpret_cast<const uint2*>(p)) : z;
    }
}

__global__ __launch_bounds__(256)
void edge_pred_kernel(const int* __restrict__ x,
                      const int* __restrict__ src,
                      const int* __restrict__ dst,
                      const int* __restrict__ neg_dst,
                      const float* __restrict__ msg,
                      const float* __restrict__ emb_type,
                      const float* __restrict__ out_w,
                      float* __restrict__ out,
                      int E) {
    const unsigned FULL = 0xffffffffu;
    int warp = (blockIdx.x * blockDim.x + threadIdx.x) >> 5;
    int lane = threadIdx.x & 31;
    if (warp >= E) return;
    int e = warp;
    int lane4 = lane * 4;

    int s  = __ldcs(src + e);
    int d  = __ldcs(dst + e);
    int nd = __ldcs(neg_dst + e);

    // Lanes 0..29 cooperatively load the three 10-int x rows.
    int which = lane / 10;          // 0:src 1:dst 2:neg
    int off   = lane - which * 10;
    int nid   = (which == 0) ? s : (which == 1) ? d : nd;
    int rv = 0;
    if (lane < 30) rv = __ldcs(x + (long long)nid * 10 + off);

    // msg dot with precomputed v (streaming; independent)
    float m = 0.f;
    if (lane < EDGE_DIM)
        m = __ldcs(msg + (long long)e * EDGE_DIM + lane) * g_v[lane];

    // ---- all types / feature indices up front (shuffles only) ----
    int t0 = __shfl_sync(FULL, rv, 0);
    int t1 = __shfl_sync(FULL, rv, 10);
    int t2 = __shfl_sync(FULL, rv, 20);
    // TYPE_PER_COL = (0,0,0,0,1,2,2,2,2)
    int h00 = (t0 == 0) ? 0 : (t0 == 1) ? 4 : 5;
    int h01 = (t1 == 0) ? 0 : (t1 == 1) ? 4 : 5;
    int h02 = (t2 == 0) ? 0 : (t2 == 1) ? 4 : 5;
    int nh0 = (t0 == 1) ? 1 : 4;
    int nh1 = (t1 == 1) ? 1 : 4;
    int nh2 = (t2 == 1) ? 1 : 4;

    int f0[4], f1[4], f2[4];
    #pragma unroll
    for (int i = 0; i < 4; i++) {
        f0[i] = __shfl_sync(FULL, rv,      h00 + i + 1);
        f1[i] = __shfl_sync(FULL, rv, 10 + h01 + i + 1);
        f2[i] = __shfl_sync(FULL, rv, 20 + h02 + i + 1);
    }

    // ---- two-node-deep pipeline: gathers of node i+1 in flight while
    //      accumulating node i (fp16 results are cheap: uint2 each) ----
    float4 a0 = ld4(emb_type + t0 * EMB + lane4);
    float4 a1 = ld4(emb_type + t1 * EMB + lane4);
    float4 a2 = ld4(emb_type + t2 * EMB + lane4);

    uint2 gA[4], gB[4];
    issue_node(gA, h00, nh0, f0, lane4);          // node0 in flight
    issue_node(gB, h01, nh1, f1, lane4);          // node1 in flight
    #pragma unroll
    for (int i = 0; i < 4; i++) acc_u2(a0, gA[i]); // consume node0
    issue_node(gA, h02, nh2, f2, lane4);          // node2 in flight
    #pragma unroll
    for (int i = 0; i < 4; i++) acc_u2(a1, gB[i]); // consume node1
    #pragma unroll
    for (int i = 0; i < 4; i++) acc_u2(a2, gA[i]); // consume node2

    float4 ow = ld4(out_w + lane4);

    float pp = fmaxf(a0.x + a1.x, 0.f) * ow.x
             + fmaxf(a0.y + a1.y, 0.f) * ow.y
             + fmaxf(a0.z + a1.z, 0.f) * ow.z
             + fmaxf(a0.w + a1.w, 0.f) * ow.w;
    float np = fmaxf(a0.x + a2.x, 0.f) * ow.x
             + fmaxf(a0.y + a2.y, 0.f) * ow.y
             + fmaxf(a0.z + a2.z, 0.f) * ow.z
             + fmaxf(a0.w + a2.w, 0.f) * ow.w;

    pp += m;
    np += m;

    #pragma unroll
    for (int o = 16; o > 0; o >>= 1) {
        pp += __shfl_xor_sync(FULL, pp, o);
        np += __shfl_xor_sync(FULL, np, o);
    }

    if (lane == 0) {
        float c = g_c;
        out[e]     = pp + c;   // pos
        out[E + e] = np + c;   // neg
    }
}

extern "C" void kernel_launch(void* const* d_in, const int* in_sizes, int n_in,
                              void* d_out, int out_size) {
    const int*   x        = (const int*)  d_in[0];
    const int*   src      = (const int*)  d_in[1];
    const int*   dst      = (const int*)  d_in[2];
    const int*   neg_dst  = (const int*)  d_in[3];
    const float* msg      = (const float*)d_in[4];
    const float* emb_type = (const float*)d_in[5];
    const float* emb_feats= (const float*)d_in[6];
    const float* edge_w   = (const float*)d_in[7];
    const float* edge_b   = (const float*)d_in[8];
    const float* out_w    = (const float*)d_in[9];
    const float* out_b    = (const float*)d_in[10];
    float* out = (float*)d_out;

    int E = in_sizes[1];

    precompute_v_kernel<<<1, 1024>>>(edge_w, edge_b, out_w, out_b);

    int conv_threads = 256;
    int conv_blocks = (TBL_ELEMS / 4 + conv_threads - 1) / conv_threads;
    convert_kernel<<<conv_blocks, conv_threads>>>(emb_feats);

    int threads = 256;
    int warps_per_block = threads / 32;
    int blocks = (E + warps_per_block - 1) / warps_per_block;
    edge_pred_kernel<<<blocks, threads>>>(x, src, dst, neg_dst, msg,
                                          emb_type, out_w, out, E);
}